// round 14
// baseline (speedup 1.0000x reference)
#include <cuda_runtime.h>
#include <cuda_fp16.h>
#include <cstdint>

// ---------------------------------------------------------------------------
// MultiHeadAttention: out = softmax((xWq^T+bq)(xWk^T+bk)^T / 8) (xWv^T+bv) Wo^T + bo
// B=2, S=2048, E=1024, H=16, D=64. fp32 gmem I/O.
// R14 = R13 with attention processing TWO 64-token KV tiles per barrier pair
// (4 stage buffers, 16 outer steps, 32 barriers instead of 64).
// ---------------------------------------------------------------------------

#define EMBED 1024
#define S_LEN 2048
#define BATCH 2
#define HEADS 16
#define HDIM 64
#define MROWS (BATCH * S_LEN)   // 4096

#define QSCALE 0.18033688011112042f   // 0.125 * log2(e)
#define ONESH2 0x3C003C00u            // half2(1.0, 1.0)

// Scratch (static device globals: no allocation anywhere)
__device__ __half g_Xh[MROWS * EMBED];
__device__ __half g_Wqh[EMBED * EMBED];
__device__ __half g_Wkh[EMBED * EMBED];
__device__ __half g_Wvh[EMBED * EMBED];
__device__ __half g_Woh[EMBED * EMBED];
__device__ __half g_Qh[MROWS * EMBED];          // [token][1024], pre-scaled by QSCALE
__device__ __half g_Kh[MROWS * EMBED];          // [token][1024]
__device__ __half g_Vh[MROWS * EMBED];          // [token][1024] (coalesced)
__device__ __half g_Ah[MROWS * EMBED];          // attention output [token][1024]

__device__ __forceinline__ void mma16(float* c,
                                      uint32_t a0, uint32_t a1, uint32_t a2, uint32_t a3,
                                      uint32_t b0, uint32_t b1) {
    asm volatile(
        "mma.sync.aligned.m16n8k16.row.col.f32.f16.f16.f32 "
        "{%0,%1,%2,%3},{%4,%5,%6,%7},{%8,%9},{%0,%1,%2,%3};"
        : "+f"(c[0]), "+f"(c[1]), "+f"(c[2]), "+f"(c[3])
        : "r"(a0), "r"(a1), "r"(a2), "r"(a3), "r"(b0), "r"(b1));
}

__device__ __forceinline__ void ldsm4(uint32_t& r0, uint32_t& r1, uint32_t& r2,
                                      uint32_t& r3, uint32_t addr) {
    asm volatile("ldmatrix.sync.aligned.m8n8.x4.shared.b16 {%0,%1,%2,%3}, [%4];"
                 : "=r"(r0), "=r"(r1), "=r"(r2), "=r"(r3) : "r"(addr));
}
__device__ __forceinline__ void ldsm4t(uint32_t& r0, uint32_t& r1, uint32_t& r2,
                                       uint32_t& r3, uint32_t addr) {
    asm volatile("ldmatrix.sync.aligned.m8n8.x4.trans.shared.b16 {%0,%1,%2,%3}, [%4];"
                 : "=r"(r0), "=r"(r1), "=r"(r2), "=r"(r3) : "r"(addr));
}

__device__ __forceinline__ void cpa16(uint32_t dst, const void* src) {
    asm volatile("cp.async.ca.shared.global [%0], [%1], 16;\n" :: "r"(dst), "l"(src));
}
__device__ __forceinline__ void cpa_commit() {
    asm volatile("cp.async.commit_group;\n" ::: "memory");
}

__device__ __forceinline__ uint32_t packh2(float lo, float hi) {
    __half2 h = __floats2half2_rn(lo, hi);
    return *reinterpret_cast<uint32_t*>(&h);
}
__device__ __forceinline__ uint32_t ex2h2(uint32_t x) {
    uint32_t r;
    asm("ex2.approx.f16x2 %0, %1;" : "=r"(r) : "r"(x));
    return r;
}

// ---------------------------------------------------------------------------
// Conversion pass: x plus four 1024x1024 weights -> fp16, single launch.
// ---------------------------------------------------------------------------
#define W4 (EMBED * EMBED / 4)          // 262144 float4 (power of 2)
#define X4 (MROWS * EMBED / 4)          // 1048576 float4

__global__ void conv_half_multi(const float4* __restrict__ sx, __half* __restrict__ dx,
                                const float4* __restrict__ s1, __half* __restrict__ d1,
                                const float4* __restrict__ s2, __half* __restrict__ d2,
                                const float4* __restrict__ s3, __half* __restrict__ d3,
                                const float4* __restrict__ s4, __half* __restrict__ d4) {
    const int total = X4 + 4 * W4;
    int i = blockIdx.x * blockDim.x + threadIdx.x;
    int stride = gridDim.x * blockDim.x;
    for (; i < total; i += stride) {
        const float4* s;
        __half* d;
        int j;
        if (i < X4) { s = sx; d = dx; j = i; }
        else {
            int k = i - X4;
            int seg = k >> 18;
            j = k & (W4 - 1);
            s = (seg == 0) ? s1 : (seg == 1) ? s2 : (seg == 2) ? s3 : s4;
            d = (seg == 0) ? d1 : (seg == 1) ? d2 : (seg == 2) ? d3 : d4;
        }
        float4 v = s[j];
        uint2 o;
        o.x = packh2(v.x, v.y);
        o.y = packh2(v.z, v.w);
        ((uint2*)d)[j] = o;
    }
}

// ---------------------------------------------------------------------------
// fp16 GEMM: C[M,1024] = X[M,1024] @ W[1024,1024]^T + bias  (NT, K-contiguous)
// Block tile 128x128, K-slab 64 halves, 256 threads (8 warps 2x4, warp 64x32).
// ldmatrix fragment loads. 2-stage cp.async double buffer (R9 ordering).
// Modes: 0=float (final), 1=half, 3=half scaled by QSCALE (Q).
// ---------------------------------------------------------------------------
#define HSTR 72                       // halves; rows 144B apart -> LDSM conflict-free
#define HROW_B (HSTR * 2)             // 144 bytes per row
#define HTILE_B (128 * HROW_B)        // 18432 bytes
#define GSMEM_B (4 * HTILE_B)         // 73728 bytes

__global__ __launch_bounds__(256, 2)
void gemm_h(const __half* __restrict__ X,
            const __half* __restrict__ W0, const float* __restrict__ B0, void* __restrict__ C0,
            const __half* __restrict__ W1, const float* __restrict__ B1, void* __restrict__ C1,
            const __half* __restrict__ W2, const float* __restrict__ B2, void* __restrict__ C2,
            int qkv) {
    const __half* W;
    const float* Bv;
    void* C;
    int mode;
    if (blockIdx.z == 0)      { W = W0; Bv = B0; C = C0; mode = qkv ? 3 : 0; }
    else if (blockIdx.z == 1) { W = W1; Bv = B1; C = C1; mode = 1; }
    else                      { W = W2; Bv = B2; C = C2; mode = 1; }

    extern __shared__ char smemc[];
    const uint32_t sBase = (uint32_t)__cvta_generic_to_shared(smemc);

    const int tid  = threadIdx.x;
    const int lane = tid & 31;
    const int warp = tid >> 5;
    const int g    = lane >> 2;
    const int qd   = lane & 3;
    const int wm   = warp >> 2;   // 0..1 -> 64 rows
    const int wn   = warp & 3;    // 0..3 -> 32 cols

    const int rowBase = blockIdx.y * 128;
    const int colBase = blockIdx.x * 128;

    // ldmatrix per-lane source coords
    const int laneA_row = lane & 15;
    const int laneA_col = (lane >> 4) << 3;              // 0 or 8 halves
    const int laneB_row = (lane & 7) | ((lane & 16) >> 1);
    const int laneB_col = lane & 8;                      // 0 or 8 halves

    const uint32_t aOff = sBase +
        (uint32_t)((wm * 64 + laneA_row) * HSTR + laneA_col) * 2;
    const uint32_t bOff = sBase + 2 * HTILE_B +
        (uint32_t)((wn * 32 + laneB_row) * HSTR + laneB_col) * 2;

    float acc[4][4][4];
#pragma unroll
    for (int mi = 0; mi < 4; mi++)
#pragma unroll
        for (int ni = 0; ni < 4; ni++)
#pragma unroll
            for (int j = 0; j < 4; j++) acc[mi][ni][j] = 0.0f;

    // stage one 128x64h tile: 1024 chunks of 16B (8 halves), 4/thread
#define H_STAGE(bufOff, srcPtr, k0)                                            \
    do {                                                                       \
        _Pragma("unroll")                                                      \
        for (int i = 0; i < 4; i++) {                                          \
            int f   = tid + i * 256;                                           \
            int r   = f >> 3;                                                  \
            int c16 = f & 7;                                                   \
            cpa16(sBase + (bufOff) + (uint32_t)(r * HSTR + c16 * 8) * 2,       \
                  (srcPtr) + (size_t)r * EMBED + (k0) + c16 * 8);              \
        }                                                                      \
    } while (0)

    H_STAGE(0 * HTILE_B, X + (size_t)rowBase * EMBED, 0);
    H_STAGE(2 * HTILE_B, W + (size_t)colBase * EMBED, 0);
    cpa_commit();

    const int NIT = EMBED / 64;  // 16
    for (int it = 0; it < NIT; it++) {
        if (it + 1 < NIT) {
            const int k0n = (it + 1) * 64;
            const int nb  = (it + 1) & 1;
            H_STAGE((uint32_t)nb * HTILE_B,       X + (size_t)rowBase * EMBED, k0n);
            H_STAGE((uint32_t)(2 + nb) * HTILE_B, W + (size_t)colBase * EMBED, k0n);
            cpa_commit();
            asm volatile("cp.async.wait_group 1;\n" ::: "memory");
        } else {
            asm volatile("cp.async.wait_group 0;\n" ::: "memory");
        }
        __syncthreads();

        const uint32_t bufB = (uint32_t)(it & 1) * HTILE_B;
        const uint32_t aB = aOff + bufB;
        const uint32_t bB = bOff + bufB;

#pragma unroll
        for (int kc = 0; kc < 4; kc++) {   // 4 k-chunks of 16 halves (32B each)
            uint32_t af[4][4];
            uint32_t bf[4][2];
#pragma unroll
            for (int mi = 0; mi < 4; mi++)
                ldsm4(af[mi][0], af[mi][1], af[mi][2], af[mi][3],
                      aB + (uint32_t)mi * 16 * HROW_B + kc * 32);
            ldsm4(bf[0][0], bf[0][1], bf[1][0], bf[1][1], bB + kc * 32);
            ldsm4(bf[2][0], bf[2][1], bf[3][0], bf[3][1],
                  bB + 16 * HROW_B + kc * 32);
#pragma unroll
            for (int mi = 0; mi < 4; mi++)
#pragma unroll
                for (int ni = 0; ni < 4; ni++)
                    mma16(acc[mi][ni], af[mi][0], af[mi][1], af[mi][2], af[mi][3],
                          bf[ni][0], bf[ni][1]);
        }
        __syncthreads();
    }

    // ---- epilogue ----
    if (mode == 0) {
        float* Cf = (float*)C;
#pragma unroll
        for (int mi = 0; mi < 4; mi++) {
            int r = rowBase + wm * 64 + mi * 16 + g;
#pragma unroll
            for (int ni = 0; ni < 4; ni++) {
                int c = colBase + wn * 32 + ni * 8 + 2 * qd;
                float b0 = Bv[c], b1 = Bv[c + 1];
                *(float2*)(Cf + (size_t)r * EMBED + c) =
                    make_float2(acc[mi][ni][0] + b0, acc[mi][ni][1] + b1);
                *(float2*)(Cf + (size_t)(r + 8) * EMBED + c) =
                    make_float2(acc[mi][ni][2] + b0, acc[mi][ni][3] + b1);
            }
        }
    } else {
        __half* Ch = (__half*)C;
        const float sc = (mode == 3) ? QSCALE : 1.0f;
#pragma unroll
        for (int mi = 0; mi < 4; mi++) {
            int r = rowBase + wm * 64 + mi * 16 + g;
#pragma unroll
            for (int ni = 0; ni < 4; ni++) {
                int c = colBase + wn * 32 + ni * 8 + 2 * qd;
                float b0 = Bv[c], b1 = Bv[c + 1];
                uint32_t v0 = packh2((acc[mi][ni][0] + b0) * sc,
                                     (acc[mi][ni][1] + b1) * sc);
                uint32_t v1 = packh2((acc[mi][ni][2] + b0) * sc,
                                     (acc[mi][ni][3] + b1) * sc);
                *(uint32_t*)(Ch + (size_t)r * EMBED + c)       = v0;
                *(uint32_t*)(Ch + (size_t)(r + 8) * EMBED + c) = v1;
            }
        }
    }
}

// ---------------------------------------------------------------------------
// fp16 flash attention (FA2): 8 warps x 16 q-rows, 64-wide KV tiles,
// ldmatrix (trans for V). 4 KV stage buffers; TWO tiles computed per barrier
// pair (16 outer steps). cp.async group covers both tiles; issue-before-wait.
// Softmax: Q pre-scaled by 0.125*log2e; p = ex2.f16x2; l via ones-column mma.
// smem: Q 18432 + 4 * (K 9216 + V 9216) = 92160 bytes; occupancy 2.
// ---------------------------------------------------------------------------
#define AQ_OFF 0
#define AKV_OFF (128 * HSTR)             // halves: KV stages start here
#define KTILE_B (64 * HROW_B)            // 9216
#define AKV_STAGE_B (2 * KTILE_B)        // 18432 (K tile then V tile)
#define ATTN_SMEM_B (HTILE_B + 4 * AKV_STAGE_B)   // 92160 bytes

__global__ __launch_bounds__(256, 2)
void attn_h(const __half* __restrict__ Q, const __half* __restrict__ K,
            const __half* __restrict__ V, __half* __restrict__ O) {
    extern __shared__ char smemc[];
    const uint32_t sBase = (uint32_t)__cvta_generic_to_shared(smemc);

    const int tid  = threadIdx.x;
    const int lane = tid & 31;
    const int warp = tid >> 5;
    const int g    = lane >> 2;
    const int qd   = lane & 3;

    const int bh = blockIdx.y;
    const int b  = bh >> 4;
    const int h  = bh & 15;
    const int q0 = blockIdx.x * 128;

    const __half* Qp = Q + ((size_t)b * S_LEN) * EMBED + h * HDIM;
    const __half* Kp = K + ((size_t)b * S_LEN) * EMBED + h * HDIM;
    const __half* Vp = V + ((size_t)b * S_LEN) * EMBED + h * HDIM;

    // ldmatrix per-lane coords
    const int laneA_row = lane & 15;
    const int laneA_col = (lane >> 4) << 3;
    const int laneB_row = (lane & 7) | ((lane & 16) >> 1);
    const int laneB_col = lane & 8;

    const uint32_t qAddr = sBase +
        (uint32_t)((warp * 16 + laneA_row) * HSTR + laneA_col) * 2;
    const uint32_t kRel = (uint32_t)(laneB_row * HSTR + laneB_col) * 2;
    // V trans-load uses the A-style lane mapping: row = t (lane&15), col = d
    const uint32_t vRel = KTILE_B + (uint32_t)(laneA_row * HSTR + laneA_col) * 2;
    const uint32_t kvBase = sBase + AKV_OFF * 2;

    // stage KV tile (K [t][d] + V [t][d]) for token offset t0 into stage st
#define KV_STAGE(st, t0)                                                       \
    do {                                                                       \
        const uint32_t so = kvBase + (uint32_t)(st) * AKV_STAGE_B;             \
        _Pragma("unroll")                                                      \
        for (int i = 0; i < 2; i++) {                                          \
            int f = tid + i * 256;                                             \
            int r = f >> 3, c16 = f & 7;                                       \
            cpa16(so + (uint32_t)(r * HSTR + c16 * 8) * 2,                     \
                  Kp + (size_t)((t0) + r) * EMBED + c16 * 8);                  \
        }                                                                      \
        _Pragma("unroll")                                                      \
        for (int i = 0; i < 2; i++) {                                          \
            int f = tid + i * 256;                                             \
            int r = f >> 3, c16 = f & 7;                                       \
            cpa16(so + KTILE_B + (uint32_t)(r * HSTR + c16 * 8) * 2,           \
                  Vp + (size_t)((t0) + r) * EMBED + c16 * 8);                  \
        }                                                                      \
    } while (0)

    // --- prologue: one group = Q + KV tiles 0,1 (stages 0,1) ---
    {
#pragma unroll
        for (int i = 0; i < 4; i++) {
            int f = tid + i * 256;
            int r = f >> 3, c16 = f & 7;
            cpa16(sBase + (uint32_t)(AQ_OFF + r * HSTR + c16 * 8) * 2,
                  Qp + (size_t)(q0 + r) * EMBED + c16 * 8);
        }
        KV_STAGE(0, 0);
        KV_STAGE(1, 64);
        cpa_commit();
    }

    float l_acc[4] = {0.0f, 0.0f, 0.0f, 0.0f};
    float o_acc[8][4];
#pragma unroll
    for (int di = 0; di < 8; di++)
#pragma unroll
        for (int j = 0; j < 4; j++) o_acc[di][j] = 0.0f;

    const int NOUT = S_LEN / 128;  // 16 outer steps, 2 tiles each
    for (int it = 0; it < NOUT; it++) {
        if (it + 1 < NOUT) {
            // prefetch tiles 2it+2, 2it+3 into the stages freed at iter it-1
            KV_STAGE((2 * it + 2) & 3, (2 * it + 2) * 64);
            KV_STAGE((2 * it + 3) & 3, (2 * it + 3) * 64);
            cpa_commit();
            asm volatile("cp.async.wait_group 1;\n" ::: "memory");
        } else {
            asm volatile("cp.async.wait_group 0;\n" ::: "memory");
        }
        __syncthreads();

#pragma unroll
        for (int half = 0; half < 2; half++) {
            const uint32_t so = kvBase + (uint32_t)((2 * it + half) & 3) * AKV_STAGE_B;
            const uint32_t kB = so + kRel;
            const uint32_t vB = so + vRel;

            // ---- S = (Q*qscale) K^T ----
            float s[8][4];
#pragma unroll
            for (int ni = 0; ni < 8; ni++)
#pragma unroll
                for (int j = 0; j < 4; j++) s[ni][j] = 0.0f;

#pragma unroll
            for (int kc = 0; kc < 4; kc++) {
                uint32_t a0, a1, a2, a3;
                ldsm4(a0, a1, a2, a3, qAddr + kc * 32);
#pragma unroll
                for (int j = 0; j < 4; j++) {
                    uint32_t b00, b01, b10, b11;
                    ldsm4(b00, b01, b10, b11, kB + (uint32_t)j * 16 * HROW_B + kc * 32);
                    mma16(s[2 * j],     a0, a1, a2, a3, b00, b01);
                    mma16(s[2 * j + 1], a0, a1, a2, a3, b10, b11);
                }
            }

            // ---- p = ex2(s) in f16x2, packed into PV A-fragments ----
            uint32_t pf[4][4];
#pragma unroll
            for (int ki = 0; ki < 4; ki++) {
                pf[ki][0] = ex2h2(packh2(s[2 * ki][0],     s[2 * ki][1]));
                pf[ki][1] = ex2h2(packh2(s[2 * ki][2],     s[2 * ki][3]));
                pf[ki][2] = ex2h2(packh2(s[2 * ki + 1][0], s[2 * ki + 1][1]));
                pf[ki][3] = ex2h2(packh2(s[2 * ki + 1][2], s[2 * ki + 1][3]));
            }

            // ---- O += P V ; l += P @ ones ----
#pragma unroll
            for (int ki = 0; ki < 4; ki++) {
                mma16(l_acc, pf[ki][0], pf[ki][1], pf[ki][2], pf[ki][3],
                      ONESH2, ONESH2);
#pragma unroll
                for (int j = 0; j < 4; j++) {
                    uint32_t b00, b01, b10, b11;
                    ldsm4t(b00, b01, b10, b11,
                           vB + (uint32_t)ki * 16 * HROW_B + (uint32_t)j * 32);
                    mma16(o_acc[2 * j],     pf[ki][0], pf[ki][1], pf[ki][2], pf[ki][3], b00, b01);
                    mma16(o_acc[2 * j + 1], pf[ki][0], pf[ki][1], pf[ki][2], pf[ki][3], b10, b11);
                }
            }
        }
        __syncthreads();  // all warps done with both stages before refill
    }

    // ---- normalize (l from ones-mma: c[0]=row g, c[2]=row g+8) + store ----
    const float rl0 = 1.0f / l_acc[0];
    const float rl1 = 1.0f / l_acc[2];
    const int rr = q0 + warp * 16 + g;
    __half* Op = O + ((size_t)b * S_LEN) * EMBED + h * HDIM;
#pragma unroll
    for (int di = 0; di < 8; di++) {
        const int c = di * 8 + 2 * qd;
        uint32_t v0 = packh2(o_acc[di][0] * rl0, o_acc[di][1] * rl0);
        uint32_t v1 = packh2(o_acc[di][2] * rl1, o_acc[di][3] * rl1);
        *(uint32_t*)(Op + (size_t)rr * EMBED + c)       = v0;
        *(uint32_t*)(Op + (size_t)(rr + 8) * EMBED + c) = v1;
    }
}

// ---------------------------------------------------------------------------
// Launch
// ---------------------------------------------------------------------------
extern "C" void kernel_launch(void* const* d_in, const int* in_sizes, int n_in,
                              void* d_out, int out_size) {
    (void)in_sizes; (void)n_in; (void)out_size;
    const float* x  = (const float*)d_in[0];
    const float* Wq = (const float*)d_in[1];
    const float* bq = (const float*)d_in[2];
    const float* Wk = (const float*)d_in[3];
    const float* bk = (const float*)d_in[4];
    const float* Wv = (const float*)d_in[5];
    const float* bv = (const float*)d_in[6];
    const float* Wo = (const float*)d_in[7];
    const float* bo = (const float*)d_in[8];
    float* out = (float*)d_out;

    __half *xh, *wqh, *wkh, *wvh, *woh, *qh, *kh, *vh, *ah;
    cudaGetSymbolAddress((void**)&xh,  g_Xh);
    cudaGetSymbolAddress((void**)&wqh, g_Wqh);
    cudaGetSymbolAddress((void**)&wkh, g_Wkh);
    cudaGetSymbolAddress((void**)&wvh, g_Wvh);
    cudaGetSymbolAddress((void**)&woh, g_Woh);
    cudaGetSymbolAddress((void**)&qh,  g_Qh);
    cudaGetSymbolAddress((void**)&kh,  g_Kh);
    cudaGetSymbolAddress((void**)&vh,  g_Vh);
    cudaGetSymbolAddress((void**)&ah,  g_Ah);

    cudaFuncSetAttribute(gemm_h, cudaFuncAttributeMaxDynamicSharedMemorySize, GSMEM_B);
    cudaFuncSetAttribute(attn_h, cudaFuncAttributeMaxDynamicSharedMemorySize, ATTN_SMEM_B);

    // 0) fp32 -> fp16 conversion of x and weights, single launch
    conv_half_multi<<<2048, 256>>>((const float4*)x,  xh,
                                   (const float4*)Wq, wqh,
                                   (const float4*)Wk, wkh,
                                   (const float4*)Wv, wvh,
                                   (const float4*)Wo, woh);

    // 1) Fused QKV projections (Q scaled fp16; K, V token-major fp16)
    gemm_h<<<dim3(EMBED / 128, MROWS / 128, 3), 256, GSMEM_B>>>(
        xh, wqh, bq, qh, wkh, bk, kh, wvh, bv, vh, /*qkv=*/1);

    // 2) Attention (fp16 in/out; V transposed in-register via ldmatrix.trans)
    attn_h<<<dim3(S_LEN / 128, BATCH * HEADS), 256, ATTN_SMEM_B>>>(qh, kh, vh, ah);

    // 3) Output projection (final fp32 output)
    gemm_h<<<dim3(EMBED / 128, MROWS / 128, 1), 256, GSMEM_B>>>(
        ah, woh, bo, out, woh, bo, out, woh, bo, out, /*qkv=*/0);
}

// round 16
// speedup vs baseline: 1.0186x; 1.0186x over previous
#include <cuda_runtime.h>
#include <cuda_fp16.h>
#include <cstdint>

// ---------------------------------------------------------------------------
// MultiHeadAttention: out = softmax((xWq^T+bq)(xWk^T+bk)^T / 8) (xWv^T+bv) Wo^T + bo
// B=2, S=2048, E=1024, H=16, D=64. fp32 gmem I/O.
// R15 = R13 attention loop with a 4-stage, SINGLE-barrier-per-step pipeline:
// prefetch tile it+2 (into the buffer whose readers are provably done via the
// previous step's sync), commit, wait_group 2, one __syncthreads, compute.
// 32 barriers instead of 64; wait granularity and ordering unchanged from R9.
// GEMM and softmax identical to R13/R12.
// ---------------------------------------------------------------------------

#define EMBED 1024
#define S_LEN 2048
#define BATCH 2
#define HEADS 16
#define HDIM 64
#define MROWS (BATCH * S_LEN)   // 4096

#define QSCALE 0.18033688011112042f   // 0.125 * log2(e)
#define ONESH2 0x3C003C00u            // half2(1.0, 1.0)

// Scratch (static device globals: no allocation anywhere)
__device__ __half g_Xh[MROWS * EMBED];
__device__ __half g_Wqh[EMBED * EMBED];
__device__ __half g_Wkh[EMBED * EMBED];
__device__ __half g_Wvh[EMBED * EMBED];
__device__ __half g_Woh[EMBED * EMBED];
__device__ __half g_Qh[MROWS * EMBED];          // [token][1024], pre-scaled by QSCALE
__device__ __half g_Kh[MROWS * EMBED];          // [token][1024]
__device__ __half g_Vh[MROWS * EMBED];          // [token][1024] (coalesced)
__device__ __half g_Ah[MROWS * EMBED];          // attention output [token][1024]

__device__ __forceinline__ void mma16(float* c,
                                      uint32_t a0, uint32_t a1, uint32_t a2, uint32_t a3,
                                      uint32_t b0, uint32_t b1) {
    asm volatile(
        "mma.sync.aligned.m16n8k16.row.col.f32.f16.f16.f32 "
        "{%0,%1,%2,%3},{%4,%5,%6,%7},{%8,%9},{%0,%1,%2,%3};"
        : "+f"(c[0]), "+f"(c[1]), "+f"(c[2]), "+f"(c[3])
        : "r"(a0), "r"(a1), "r"(a2), "r"(a3), "r"(b0), "r"(b1));
}

__device__ __forceinline__ void ldsm4(uint32_t& r0, uint32_t& r1, uint32_t& r2,
                                      uint32_t& r3, uint32_t addr) {
    asm volatile("ldmatrix.sync.aligned.m8n8.x4.shared.b16 {%0,%1,%2,%3}, [%4];"
                 : "=r"(r0), "=r"(r1), "=r"(r2), "=r"(r3) : "r"(addr));
}
__device__ __forceinline__ void ldsm4t(uint32_t& r0, uint32_t& r1, uint32_t& r2,
                                       uint32_t& r3, uint32_t addr) {
    asm volatile("ldmatrix.sync.aligned.m8n8.x4.trans.shared.b16 {%0,%1,%2,%3}, [%4];"
                 : "=r"(r0), "=r"(r1), "=r"(r2), "=r"(r3) : "r"(addr));
}

__device__ __forceinline__ void cpa16(uint32_t dst, const void* src) {
    asm volatile("cp.async.ca.shared.global [%0], [%1], 16;\n" :: "r"(dst), "l"(src));
}
__device__ __forceinline__ void cpa_commit() {
    asm volatile("cp.async.commit_group;\n" ::: "memory");
}

__device__ __forceinline__ uint32_t packh2(float lo, float hi) {
    __half2 h = __floats2half2_rn(lo, hi);
    return *reinterpret_cast<uint32_t*>(&h);
}
__device__ __forceinline__ uint32_t ex2h2(uint32_t x) {
    uint32_t r;
    asm("ex2.approx.f16x2 %0, %1;" : "=r"(r) : "r"(x));
    return r;
}

// ---------------------------------------------------------------------------
// Conversion pass: x plus four 1024x1024 weights -> fp16, single launch.
// ---------------------------------------------------------------------------
#define W4 (EMBED * EMBED / 4)          // 262144 float4 (power of 2)
#define X4 (MROWS * EMBED / 4)          // 1048576 float4

__global__ void conv_half_multi(const float4* __restrict__ sx, __half* __restrict__ dx,
                                const float4* __restrict__ s1, __half* __restrict__ d1,
                                const float4* __restrict__ s2, __half* __restrict__ d2,
                                const float4* __restrict__ s3, __half* __restrict__ d3,
                                const float4* __restrict__ s4, __half* __restrict__ d4) {
    const int total = X4 + 4 * W4;
    int i = blockIdx.x * blockDim.x + threadIdx.x;
    int stride = gridDim.x * blockDim.x;
    for (; i < total; i += stride) {
        const float4* s;
        __half* d;
        int j;
        if (i < X4) { s = sx; d = dx; j = i; }
        else {
            int k = i - X4;
            int seg = k >> 18;
            j = k & (W4 - 1);
            s = (seg == 0) ? s1 : (seg == 1) ? s2 : (seg == 2) ? s3 : s4;
            d = (seg == 0) ? d1 : (seg == 1) ? d2 : (seg == 2) ? d3 : d4;
        }
        float4 v = s[j];
        uint2 o;
        o.x = packh2(v.x, v.y);
        o.y = packh2(v.z, v.w);
        ((uint2*)d)[j] = o;
    }
}

// ---------------------------------------------------------------------------
// fp16 GEMM: C[M,1024] = X[M,1024] @ W[1024,1024]^T + bias  (NT, K-contiguous)
// Block tile 128x128, K-slab 64 halves, 256 threads (8 warps 2x4, warp 64x32).
// ldmatrix fragment loads. 2-stage cp.async double buffer (R9 ordering).
// Modes: 0=float (final), 1=half, 3=half scaled by QSCALE (Q).
// ---------------------------------------------------------------------------
#define HSTR 72                       // halves; rows 144B apart -> LDSM conflict-free
#define HROW_B (HSTR * 2)             // 144 bytes per row
#define HTILE_B (128 * HROW_B)        // 18432 bytes
#define GSMEM_B (4 * HTILE_B)         // 73728 bytes

__global__ __launch_bounds__(256, 2)
void gemm_h(const __half* __restrict__ X,
            const __half* __restrict__ W0, const float* __restrict__ B0, void* __restrict__ C0,
            const __half* __restrict__ W1, const float* __restrict__ B1, void* __restrict__ C1,
            const __half* __restrict__ W2, const float* __restrict__ B2, void* __restrict__ C2,
            int qkv) {
    const __half* W;
    const float* Bv;
    void* C;
    int mode;
    if (blockIdx.z == 0)      { W = W0; Bv = B0; C = C0; mode = qkv ? 3 : 0; }
    else if (blockIdx.z == 1) { W = W1; Bv = B1; C = C1; mode = 1; }
    else                      { W = W2; Bv = B2; C = C2; mode = 1; }

    extern __shared__ char smemc[];
    const uint32_t sBase = (uint32_t)__cvta_generic_to_shared(smemc);

    const int tid  = threadIdx.x;
    const int lane = tid & 31;
    const int warp = tid >> 5;
    const int g    = lane >> 2;
    const int qd   = lane & 3;
    const int wm   = warp >> 2;   // 0..1 -> 64 rows
    const int wn   = warp & 3;    // 0..3 -> 32 cols

    const int rowBase = blockIdx.y * 128;
    const int colBase = blockIdx.x * 128;

    // ldmatrix per-lane source coords
    const int laneA_row = lane & 15;
    const int laneA_col = (lane >> 4) << 3;              // 0 or 8 halves
    const int laneB_row = (lane & 7) | ((lane & 16) >> 1);
    const int laneB_col = lane & 8;                      // 0 or 8 halves

    const uint32_t aOff = sBase +
        (uint32_t)((wm * 64 + laneA_row) * HSTR + laneA_col) * 2;
    const uint32_t bOff = sBase + 2 * HTILE_B +
        (uint32_t)((wn * 32 + laneB_row) * HSTR + laneB_col) * 2;

    float acc[4][4][4];
#pragma unroll
    for (int mi = 0; mi < 4; mi++)
#pragma unroll
        for (int ni = 0; ni < 4; ni++)
#pragma unroll
            for (int j = 0; j < 4; j++) acc[mi][ni][j] = 0.0f;

    // stage one 128x64h tile: 1024 chunks of 16B (8 halves), 4/thread
#define H_STAGE(bufOff, srcPtr, k0)                                            \
    do {                                                                       \
        _Pragma("unroll")                                                      \
        for (int i = 0; i < 4; i++) {                                          \
            int f   = tid + i * 256;                                           \
            int r   = f >> 3;                                                  \
            int c16 = f & 7;                                                   \
            cpa16(sBase + (bufOff) + (uint32_t)(r * HSTR + c16 * 8) * 2,       \
                  (srcPtr) + (size_t)r * EMBED + (k0) + c16 * 8);              \
        }                                                                      \
    } while (0)

    H_STAGE(0 * HTILE_B, X + (size_t)rowBase * EMBED, 0);
    H_STAGE(2 * HTILE_B, W + (size_t)colBase * EMBED, 0);
    cpa_commit();

    const int NIT = EMBED / 64;  // 16
    for (int it = 0; it < NIT; it++) {
        if (it + 1 < NIT) {
            const int k0n = (it + 1) * 64;
            const int nb  = (it + 1) & 1;
            H_STAGE((uint32_t)nb * HTILE_B,       X + (size_t)rowBase * EMBED, k0n);
            H_STAGE((uint32_t)(2 + nb) * HTILE_B, W + (size_t)colBase * EMBED, k0n);
            cpa_commit();
            asm volatile("cp.async.wait_group 1;\n" ::: "memory");
        } else {
            asm volatile("cp.async.wait_group 0;\n" ::: "memory");
        }
        __syncthreads();

        const uint32_t bufB = (uint32_t)(it & 1) * HTILE_B;
        const uint32_t aB = aOff + bufB;
        const uint32_t bB = bOff + bufB;

#pragma unroll
        for (int kc = 0; kc < 4; kc++) {   // 4 k-chunks of 16 halves (32B each)
            uint32_t af[4][4];
            uint32_t bf[4][2];
#pragma unroll
            for (int mi = 0; mi < 4; mi++)
                ldsm4(af[mi][0], af[mi][1], af[mi][2], af[mi][3],
                      aB + (uint32_t)mi * 16 * HROW_B + kc * 32);
            ldsm4(bf[0][0], bf[0][1], bf[1][0], bf[1][1], bB + kc * 32);
            ldsm4(bf[2][0], bf[2][1], bf[3][0], bf[3][1],
                  bB + 16 * HROW_B + kc * 32);
#pragma unroll
            for (int mi = 0; mi < 4; mi++)
#pragma unroll
                for (int ni = 0; ni < 4; ni++)
                    mma16(acc[mi][ni], af[mi][0], af[mi][1], af[mi][2], af[mi][3],
                          bf[ni][0], bf[ni][1]);
        }
        __syncthreads();
    }

    // ---- epilogue ----
    if (mode == 0) {
        float* Cf = (float*)C;
#pragma unroll
        for (int mi = 0; mi < 4; mi++) {
            int r = rowBase + wm * 64 + mi * 16 + g;
#pragma unroll
            for (int ni = 0; ni < 4; ni++) {
                int c = colBase + wn * 32 + ni * 8 + 2 * qd;
                float b0 = Bv[c], b1 = Bv[c + 1];
                *(float2*)(Cf + (size_t)r * EMBED + c) =
                    make_float2(acc[mi][ni][0] + b0, acc[mi][ni][1] + b1);
                *(float2*)(Cf + (size_t)(r + 8) * EMBED + c) =
                    make_float2(acc[mi][ni][2] + b0, acc[mi][ni][3] + b1);
            }
        }
    } else {
        __half* Ch = (__half*)C;
        const float sc = (mode == 3) ? QSCALE : 1.0f;
#pragma unroll
        for (int mi = 0; mi < 4; mi++) {
            int r = rowBase + wm * 64 + mi * 16 + g;
#pragma unroll
            for (int ni = 0; ni < 4; ni++) {
                int c = colBase + wn * 32 + ni * 8 + 2 * qd;
                float b0 = Bv[c], b1 = Bv[c + 1];
                uint32_t v0 = packh2((acc[mi][ni][0] + b0) * sc,
                                     (acc[mi][ni][1] + b1) * sc);
                uint32_t v1 = packh2((acc[mi][ni][2] + b0) * sc,
                                     (acc[mi][ni][3] + b1) * sc);
                *(uint32_t*)(Ch + (size_t)r * EMBED + c)       = v0;
                *(uint32_t*)(Ch + (size_t)(r + 8) * EMBED + c) = v1;
            }
        }
    }
}

// ---------------------------------------------------------------------------
// fp16 flash attention (FA2): 8 warps x 16 q-rows, 64-wide KV tiles,
// ldmatrix (trans for V). 4 KV stage buffers, ONE __syncthreads per step:
//   iter it: prefetch tile it+2 into buf[(it+2)&3] (its readers finished at
//   it-2 and passed iter it-1's sync before this issue point), commit,
//   wait_group 2 (tiles it+1, it+2 may stay pending), sync, compute tile it.
// Softmax: Q pre-scaled by 0.125*log2e; p = ex2.f16x2; l via ones-column mma.
// smem: Q 18432 + 4 * (K 9216 + V 9216) = 92160 bytes; occupancy 2.
// ---------------------------------------------------------------------------
#define AQ_OFF 0
#define AKV_OFF (128 * HSTR)             // halves: KV stages start here
#define KTILE_B (64 * HROW_B)            // 9216
#define AKV_STAGE_B (2 * KTILE_B)        // 18432 (K tile then V tile)
#define ATTN_SMEM_B (HTILE_B + 4 * AKV_STAGE_B)   // 92160 bytes

__global__ __launch_bounds__(256, 2)
void attn_h(const __half* __restrict__ Q, const __half* __restrict__ K,
            const __half* __restrict__ V, __half* __restrict__ O) {
    extern __shared__ char smemc[];
    const uint32_t sBase = (uint32_t)__cvta_generic_to_shared(smemc);

    const int tid  = threadIdx.x;
    const int lane = tid & 31;
    const int warp = tid >> 5;
    const int g    = lane >> 2;
    const int qd   = lane & 3;

    const int bh = blockIdx.y;
    const int b  = bh >> 4;
    const int h  = bh & 15;
    const int q0 = blockIdx.x * 128;

    const __half* Qp = Q + ((size_t)b * S_LEN) * EMBED + h * HDIM;
    const __half* Kp = K + ((size_t)b * S_LEN) * EMBED + h * HDIM;
    const __half* Vp = V + ((size_t)b * S_LEN) * EMBED + h * HDIM;

    // ldmatrix per-lane coords
    const int laneA_row = lane & 15;
    const int laneA_col = (lane >> 4) << 3;
    const int laneB_row = (lane & 7) | ((lane & 16) >> 1);
    const int laneB_col = lane & 8;

    const uint32_t qAddr = sBase +
        (uint32_t)((warp * 16 + laneA_row) * HSTR + laneA_col) * 2;
    const uint32_t kRel = (uint32_t)(laneB_row * HSTR + laneB_col) * 2;
    // V trans-load uses the A-style lane mapping: row = t (lane&15), col = d
    const uint32_t vRel = KTILE_B + (uint32_t)(laneA_row * HSTR + laneA_col) * 2;
    const uint32_t kvBase = sBase + AKV_OFF * 2;

    // stage KV tile (K [t][d] + V [t][d]) for token offset t0 into stage st
#define KV_STAGE(st, t0)                                                       \
    do {                                                                       \
        const uint32_t so = kvBase + (uint32_t)(st) * AKV_STAGE_B;             \
        _Pragma("unroll")                                                      \
        for (int i = 0; i < 2; i++) {                                          \
            int f = tid + i * 256;                                             \
            int r = f >> 3, c16 = f & 7;                                       \
            cpa16(so + (uint32_t)(r * HSTR + c16 * 8) * 2,                     \
                  Kp + (size_t)((t0) + r) * EMBED + c16 * 8);                  \
        }                                                                      \
        _Pragma("unroll")                                                      \
        for (int i = 0; i < 2; i++) {                                          \
            int f = tid + i * 256;                                             \
            int r = f >> 3, c16 = f & 7;                                       \
            cpa16(so + KTILE_B + (uint32_t)(r * HSTR + c16 * 8) * 2,           \
                  Vp + (size_t)((t0) + r) * EMBED + c16 * 8);                  \
        }                                                                      \
    } while (0)

    // --- prologue: group 0 = Q + KV tile 0 (stage 0); group 1 = KV tile 1 ---
    {
#pragma unroll
        for (int i = 0; i < 4; i++) {
            int f = tid + i * 256;
            int r = f >> 3, c16 = f & 7;
            cpa16(sBase + (uint32_t)(AQ_OFF + r * HSTR + c16 * 8) * 2,
                  Qp + (size_t)(q0 + r) * EMBED + c16 * 8);
        }
        KV_STAGE(0, 0);
        cpa_commit();
        KV_STAGE(1, 64);
        cpa_commit();
    }

    float l_acc[4] = {0.0f, 0.0f, 0.0f, 0.0f};
    float o_acc[8][4];
#pragma unroll
    for (int di = 0; di < 8; di++)
#pragma unroll
        for (int j = 0; j < 4; j++) o_acc[di][j] = 0.0f;

    const int NSTEP = S_LEN / 64;  // 32
    for (int it = 0; it < NSTEP; it++) {
        if (it + 2 < NSTEP) {
            // buf[(it+2)&3] == buf[(it-2)&3]: its readers (iter it-2) all
            // passed iter it-1's __syncthreads before we reach this issue.
            KV_STAGE((it + 2) & 3, (it + 2) * 64);
            cpa_commit();
            asm volatile("cp.async.wait_group 2;\n" ::: "memory");
        } else if (it + 1 < NSTEP) {
            asm volatile("cp.async.wait_group 1;\n" ::: "memory");
        } else {
            asm volatile("cp.async.wait_group 0;\n" ::: "memory");
        }
        __syncthreads();   // the ONLY barrier per step

        const uint32_t so = kvBase + (uint32_t)(it & 3) * AKV_STAGE_B;
        const uint32_t kB = so + kRel;
        const uint32_t vB = so + vRel;

        // ---- S = (Q*qscale) K^T ----
        float s[8][4];
#pragma unroll
        for (int ni = 0; ni < 8; ni++)
#pragma unroll
            for (int j = 0; j < 4; j++) s[ni][j] = 0.0f;

#pragma unroll
        for (int kc = 0; kc < 4; kc++) {
            uint32_t a0, a1, a2, a3;
            ldsm4(a0, a1, a2, a3, qAddr + kc * 32);
#pragma unroll
            for (int j = 0; j < 4; j++) {
                uint32_t b00, b01, b10, b11;
                ldsm4(b00, b01, b10, b11, kB + (uint32_t)j * 16 * HROW_B + kc * 32);
                mma16(s[2 * j],     a0, a1, a2, a3, b00, b01);
                mma16(s[2 * j + 1], a0, a1, a2, a3, b10, b11);
            }
        }

        // ---- p = ex2(s) in f16x2, packed into PV A-fragments ----
        uint32_t pf[4][4];
#pragma unroll
        for (int ki = 0; ki < 4; ki++) {
            pf[ki][0] = ex2h2(packh2(s[2 * ki][0],     s[2 * ki][1]));
            pf[ki][1] = ex2h2(packh2(s[2 * ki][2],     s[2 * ki][3]));
            pf[ki][2] = ex2h2(packh2(s[2 * ki + 1][0], s[2 * ki + 1][1]));
            pf[ki][3] = ex2h2(packh2(s[2 * ki + 1][2], s[2 * ki + 1][3]));
        }

        // ---- O += P V ; l += P @ ones (tensor-core rowsum, fp32 exact) ----
#pragma unroll
        for (int ki = 0; ki < 4; ki++) {
            mma16(l_acc, pf[ki][0], pf[ki][1], pf[ki][2], pf[ki][3],
                  ONESH2, ONESH2);
#pragma unroll
            for (int j = 0; j < 4; j++) {
                uint32_t b00, b01, b10, b11;
                ldsm4t(b00, b01, b10, b11,
                       vB + (uint32_t)ki * 16 * HROW_B + (uint32_t)j * 32);
                mma16(o_acc[2 * j],     pf[ki][0], pf[ki][1], pf[ki][2], pf[ki][3], b00, b01);
                mma16(o_acc[2 * j + 1], pf[ki][0], pf[ki][1], pf[ki][2], pf[ki][3], b10, b11);
            }
        }
        // no end-of-step barrier: buffer reuse is protected by the NEXT
        // step's single sync (issue at it+1 targets buf[(it+3)&3], whose
        // readers finished at it-1 and passed THIS step's sync).
    }

    // ---- normalize (l from ones-mma: c[0]=row g, c[2]=row g+8) + store ----
    const float rl0 = 1.0f / l_acc[0];
    const float rl1 = 1.0f / l_acc[2];
    const int rr = q0 + warp * 16 + g;
    __half* Op = O + ((size_t)b * S_LEN) * EMBED + h * HDIM;
#pragma unroll
    for (int di = 0; di < 8; di++) {
        const int c = di * 8 + 2 * qd;
        uint32_t v0 = packh2(o_acc[di][0] * rl0, o_acc[di][1] * rl0);
        uint32_t v1 = packh2(o_acc[di][2] * rl1, o_acc[di][3] * rl1);
        *(uint32_t*)(Op + (size_t)rr * EMBED + c)       = v0;
        *(uint32_t*)(Op + (size_t)(rr + 8) * EMBED + c) = v1;
    }
}

// ---------------------------------------------------------------------------
// Launch
// ---------------------------------------------------------------------------
extern "C" void kernel_launch(void* const* d_in, const int* in_sizes, int n_in,
                              void* d_out, int out_size) {
    (void)in_sizes; (void)n_in; (void)out_size;
    const float* x  = (const float*)d_in[0];
    const float* Wq = (const float*)d_in[1];
    const float* bq = (const float*)d_in[2];
    const float* Wk = (const float*)d_in[3];
    const float* bk = (const float*)d_in[4];
    const float* Wv = (const float*)d_in[5];
    const float* bv = (const float*)d_in[6];
    const float* Wo = (const float*)d_in[7];
    const float* bo = (const float*)d_in[8];
    float* out = (float*)d_out;

    __half *xh, *wqh, *wkh, *wvh, *woh, *qh, *kh, *vh, *ah;
    cudaGetSymbolAddress((void**)&xh,  g_Xh);
    cudaGetSymbolAddress((void**)&wqh, g_Wqh);
    cudaGetSymbolAddress((void**)&wkh, g_Wkh);
    cudaGetSymbolAddress((void**)&wvh, g_Wvh);
    cudaGetSymbolAddress((void**)&woh, g_Woh);
    cudaGetSymbolAddress((void**)&qh,  g_Qh);
    cudaGetSymbolAddress((void**)&kh,  g_Kh);
    cudaGetSymbolAddress((void**)&vh,  g_Vh);
    cudaGetSymbolAddress((void**)&ah,  g_Ah);

    cudaFuncSetAttribute(gemm_h, cudaFuncAttributeMaxDynamicSharedMemorySize, GSMEM_B);
    cudaFuncSetAttribute(attn_h, cudaFuncAttributeMaxDynamicSharedMemorySize, ATTN_SMEM_B);

    // 0) fp32 -> fp16 conversion of x and weights, single launch
    conv_half_multi<<<2960, 256>>>((const float4*)x,  xh,
                                   (const float4*)Wq, wqh,
                                   (const float4*)Wk, wkh,
                                   (const float4*)Wv, wvh,
                                   (const float4*)Wo, woh);

    // 1) Fused QKV projections (Q scaled fp16; K, V token-major fp16)
    gemm_h<<<dim3(EMBED / 128, MROWS / 128, 3), 256, GSMEM_B>>>(
        xh, wqh, bq, qh, wkh, bk, kh, wvh, bv, vh, /*qkv=*/1);

    // 2) Attention (fp16 in/out; V transposed in-register via ldmatrix.trans)
    attn_h<<<dim3(S_LEN / 128, BATCH * HEADS), 256, ATTN_SMEM_B>>>(qh, kh, vh, ah);

    // 3) Output projection (final fp32 output)
    gemm_h<<<dim3(EMBED / 128, MROWS / 128, 1), 256, GSMEM_B>>>(
        ah, woh, bo, out, woh, bo, out, woh, bo, out, /*qkv=*/0);
}